// round 17
// baseline (speedup 1.0000x reference)
#include <cuda_runtime.h>
#include <math.h>

// Problem constants
#define Bc 64
#define Tc 128
#define Dc 1024
#define MU 8192            // B*T rows of xs

#define NBLK 128                   // one wave on 148 SMs
#define ROWS_PER_BLK 64            // 2 blocks per batch
#define THR 512

// Scratch (device globals: allocation-free per harness rules)
__device__ float g_xs[MU];
__device__ float g_partial[2 * Bc];
__device__ unsigned int g_cnt[Bc];   // per-batch producer counters (reset each run)
__device__ unsigned int g_done2;     // loss-complete counter (reset each run)

// ---------------------------------------------------------------------------
// Single launch, ONE WAVE (128 CTAs x 512 thr), fan-in 2 per batch.
// Phase 1: block bid does 64 rows of batch bid/2 (half bid&1).
//   8 threads per row; each thread: 32 data float4 + 32 weight float4
//   (weights 2KB -> L1-resident), 4 chunks of 8 independent LDG.128 (MLP=8),
//   single-scalar accumulator, 3-step shfl reduction over 8 lanes.
// Phase 2 (even blocks, warp 0): spin on g_cnt[b]==2 (nanosleep backoff),
//   then batch b's loss:
//   loss_row(j) = log( sum_{t=j+2}^{len-1} exp(xs_t - M) ) + M - xs_{j+2}
//   (LSTM head + fc_b cancel along the softmax axis -> dead inputs.)
// Phase 3 (last of the 64): fixed-order fold of 64 partials -> out, reset.
// ---------------------------------------------------------------------------
__global__ __launch_bounds__(THR) void fused_kernel(const float* __restrict__ x,
                                                    const float* __restrict__ fc_w,
                                                    const int* __restrict__ mask,
                                                    float* __restrict__ out) {
    const int tid  = threadIdx.x;
    const int lane = tid & 31;
    const int warp = tid >> 5;
    const int bid  = blockIdx.x;
    const int batch = bid >> 1;
    const bool designated = ((bid & 1) == 0);

    // Prefetch mask for designated blocks (latency hidden behind xs phase)
    int4 mv = make_int4(0, 0, 0, 0);
    if (designated && warp == 0)
        mv = ((const int4*)(mask + batch * Tc))[lane];

    // ---- Phase 1: 64 rows, 8 threads per row ----
    {
        const int lr = tid >> 3;          // 0..63 local row
        const int q  = tid & 7;           // sub-column 0..7
        const int gr = batch * Tc + (bid & 1) * ROWS_PER_BLK + lr;
        const float4* xrow = (const float4*)(x + (size_t)gr * Dc);
        const float4* wxv  = (const float4*)(fc_w + 512);

        float acc = 0.f;
#pragma unroll
        for (int ch = 0; ch < 4; ch++) {
            float4 a[8], w[8];
#pragma unroll
            for (int k = 0; k < 8; k++)
                a[k] = xrow[q + (ch * 8 + k) * 8];      // 8 independent LDG.128
#pragma unroll
            for (int k = 0; k < 8; k++)
                w[k] = __ldg(&wxv[q + (ch * 8 + k) * 8]); // L1-resident weights
#pragma unroll
            for (int k = 0; k < 8; k++)
                acc += a[k].x * w[k].x + a[k].y * w[k].y
                     + a[k].z * w[k].z + a[k].w * w[k].w;
        }

        // reduce over the 8 lanes sharing this row (lanes q..q+7 aligned)
        acc += __shfl_down_sync(0xffffffffu, acc, 4);
        acc += __shfl_down_sync(0xffffffffu, acc, 2);
        acc += __shfl_down_sync(0xffffffffu, acc, 1);
        if (q == 0) g_xs[gr] = acc;
    }

    __syncthreads();
    if (tid == 0) {
        __threadfence();                 // publish this block's g_xs slice
        atomicAdd(&g_cnt[batch], 1u);
    }

    if (!designated || warp != 0) return;   // only warp 0 of even blocks continue

    // ---- Phase 2: wait for THIS batch's 2 producers, then its loss ----
    {
        volatile unsigned int* cnt = &g_cnt[batch];
        while (*cnt < 2u) __nanosleep(32);
    }
    __threadfence();                     // acquire this batch's g_xs rows
    __syncwarp();

    const int b = batch;

    int len = mv.x + mv.y + mv.z + mv.w;
#pragma unroll
    for (int off = 16; off; off >>= 1)
        len += __shfl_xor_sync(0xffffffffu, len, off);

    float v[4];
#pragma unroll
    for (int c = 0; c < 4; c++)
        v[c] = g_xs[b * Tc + c * 32 + lane];

    // per-batch max (constant shift; xs is O(1) so no overflow risk)
    float M = fmaxf(fmaxf(v[0], v[1]), fmaxf(v[2], v[3]));
#pragma unroll
    for (int off = 16; off; off >>= 1)
        M = fmaxf(M, __shfl_xor_sync(0xffffffffu, M, off));

    float e[4];
#pragma unroll
    for (int c = 0; c < 4; c++) {
        const int t = c * 32 + lane;
        e[c] = (t < len) ? __expf(v[c] - M) : 0.f;
    }

    // suffix-sum scan, chunk 3 -> 0, carry = sum of later chunks
    float acc = 0.f;
    float carry = 0.f;
#pragma unroll
    for (int c = 3; c >= 0; c--) {
        float ss = e[c];
#pragma unroll
        for (int off = 1; off < 32; off <<= 1) {
            float s2 = __shfl_down_sync(0xffffffffu, ss, off);
            ss += ((lane + off) < 32) ? s2 : 0.f;
        }
        ss += carry;
        const int t = c * 32 + lane;
        if (t >= 2 && t < len)
            acc += __logf(ss) + M - v[c];
        carry = __shfl_sync(0xffffffffu, ss, 0);
    }

    // warp-reduce acc (fixed order -> deterministic)
#pragma unroll
    for (int off = 16; off; off >>= 1)
        acc += __shfl_xor_sync(0xffffffffu, acc, off);

    unsigned int done2 = 0;
    if (lane == 0) {
        int cnt = len - 2;
        if (cnt < 0) cnt = 0;
        g_partial[2 * b]     = acc;
        g_partial[2 * b + 1] = (float)cnt;
        __threadfence();
        done2 = atomicAdd(&g_done2, 1u);
    }
    done2 = __shfl_sync(0xffffffffu, done2, 0);
    if (done2 != Bc - 1) return;

    // ---- Phase 3: last loss-warp folds the 64 partials (whole warp) ----
    __threadfence();
    float tot = g_partial[2 * lane]     + g_partial[2 * (lane + 32)];
    float cnt = g_partial[2 * lane + 1] + g_partial[2 * (lane + 32) + 1];
#pragma unroll
    for (int off = 16; off; off >>= 1) {
        tot += __shfl_xor_sync(0xffffffffu, tot, off);
        cnt += __shfl_xor_sync(0xffffffffu, cnt, off);
    }
    // reset counters for next graph replay (this warp runs strictly last)
    g_cnt[lane] = 0;
    g_cnt[lane + 32] = 0;
    if (lane == 0) {
        out[0] = (cnt > 0.f) ? tot / cnt : 0.f;
        g_done2 = 0;
    }
}

// ---------------------------------------------------------------------------
extern "C" void kernel_launch(void* const* d_in, const int* in_sizes, int n_in,
                              void* d_out, int out_size) {
    const float* x    = (const float*)d_in[0];
    const int*   mask = (const int*)d_in[1];
    // d_in[2..5] (W_ih, W_hh, b_ih, b_hh) and fc_b are dead: the LSTM head
    // contribution is constant along the logsumexp axis and cancels exactly.
    const float* fc_w = (const float*)d_in[6];
    float* out = (float*)d_out;

    fused_kernel<<<NBLK, THR>>>(x, fc_w, mask, out);
}